// round 1
// baseline (speedup 1.0000x reference)
#include <cuda_runtime.h>
#include <cuda_bf16.h>

// LinearSpline: out = lerp(coef[idx], coef[idx+1], frac) with
//   xs   = x * scale[c]
//   xc   = clip(xs, -GRID*25, GRID*24)
//   fl   = floor(xc / GRID)
//   frac = xs / GRID - fl          (UNclamped xs, per reference)
//   idx  = c*51 + 25 + (int)fl
//   out  = result / scale[c]
//
// x: [32, 64, 128, 128] fp32; coef: [64*51] fp32; scale: [1,64,1,1] fp32 (ones).
// Pure HBM-bound elementwise op: 128 MiB in + 128 MiB out.

#define NUM_ACT 64
#define SIZE    51
#define TABLE   (NUM_ACT * SIZE)   // 3264

// Constants derived exactly as the reference does (double -> float casts)
#define GRID_D  (8.0 / 50.0)                       // 0.16 in double
__device__ __forceinline__ float grid_f()  { return (float)GRID_D; }
__device__ __forceinline__ float lo_f()    { return (float)(-GRID_D * 25.0); }
__device__ __forceinline__ float hi_f()    { return (float)( GRID_D * 24.0); }

__global__ __launch_bounds__(256, 8)
void linear_spline_kernel(const float4* __restrict__ x,
                          const float*  __restrict__ coef,
                          const float*  __restrict__ scale,
                          float4*       __restrict__ out,
                          int n4)
{
    // Pair table: sc[i] = (coef[i], coef[i+1]) -> one LDS.64 per gather.
    __shared__ float2 sc[TABLE];
    __shared__ float  ssc[NUM_ACT];

    for (int i = threadIdx.x; i < TABLE; i += blockDim.x) {
        float a = coef[i];
        float b = (i + 1 < TABLE) ? coef[i + 1] : 0.0f;  // i=3263 edge never used with idx+1
        sc[i] = make_float2(a, b);
    }
    for (int i = threadIdx.x; i < NUM_ACT; i += blockDim.x) {
        ssc[i] = scale[i];
    }
    __syncthreads();

    const float g  = grid_f();
    const float lo = lo_f();
    const float hi = hi_f();

    const int stride = gridDim.x * blockDim.x;
    for (int i = blockIdx.x * blockDim.x + threadIdx.x; i < n4; i += stride) {
        float4 xv = x[i];
        // 128*128/4 = 4096 = 2^12 float4 per channel, 64 channels per image
        const int c  = (i >> 12) & (NUM_ACT - 1);
        const float s = ssc[c];
        const int zk = c * SIZE + SIZE / 2;

        float4 o;
        {
            float xs = xv.x * s;
            float xc = fminf(fmaxf(xs, lo), hi);
            float fl = floorf(xc / g);
            float fr = xs / g - fl;
            float2 cp = sc[zk + (int)fl];
            o.x = (cp.y * fr + cp.x * (1.0f - fr)) / s;
        }
        {
            float xs = xv.y * s;
            float xc = fminf(fmaxf(xs, lo), hi);
            float fl = floorf(xc / g);
            float fr = xs / g - fl;
            float2 cp = sc[zk + (int)fl];
            o.y = (cp.y * fr + cp.x * (1.0f - fr)) / s;
        }
        {
            float xs = xv.z * s;
            float xc = fminf(fmaxf(xs, lo), hi);
            float fl = floorf(xc / g);
            float fr = xs / g - fl;
            float2 cp = sc[zk + (int)fl];
            o.z = (cp.y * fr + cp.x * (1.0f - fr)) / s;
        }
        {
            float xs = xv.w * s;
            float xc = fminf(fmaxf(xs, lo), hi);
            float fl = floorf(xc / g);
            float fr = xs / g - fl;
            float2 cp = sc[zk + (int)fl];
            o.w = (cp.y * fr + cp.x * (1.0f - fr)) / s;
        }
        out[i] = o;
    }
}

extern "C" void kernel_launch(void* const* d_in, const int* in_sizes, int n_in,
                              void* d_out, int out_size)
{
    const float* x     = (const float*)d_in[0];
    const float* coef  = (const float*)d_in[1];
    const float* scale = (const float*)d_in[2];
    float* out         = (float*)d_out;

    const int n  = in_sizes[0];      // 33,554,432
    const int n4 = n / 4;            // 8,388,608

    const int threads = 256;
    const int blocks  = 148 * 8;     // 8 CTAs/SM, grid-stride (~28 iters/thread)

    linear_spline_kernel<<<blocks, threads>>>(
        (const float4*)x, coef, scale, (float4*)out, n4);
}

// round 2
// speedup vs baseline: 1.3020x; 1.3020x over previous
#include <cuda_runtime.h>
#include <cuda_bf16.h>

// LinearSpline activation, division-free formulation:
//   t  = (x*s) * 6.25f                      (6.25f == nearest-float(1/0.16f), exact)
//   tc = clamp(t, -25.0f, 24.0f)            (== reference clip-then-divide at all boundaries)
//   fl = floor(tc);  fr = t - fl            (fr uses unclamped t, per reference)
//   out = fma(fr, c[z+fl+1]-c[z+fl], c[z+fl]) * (1/s)
//
// x: [32,64,128,128] fp32 -> 128 MiB in + 128 MiB out, pure HBM-bound target.
// Coefficient pair table (c[i], c[i+1]) lives in SMEM: one LDS.64 per gather.

#define NUM_ACT 64
#define SIZE    51
#define TABLE   (NUM_ACT * SIZE)   // 3264

__global__ __launch_bounds__(256, 6)
void linear_spline_kernel(const float4* __restrict__ x,
                          const float*  __restrict__ coef,
                          const float*  __restrict__ scale,
                          float4*       __restrict__ out,
                          int n4)
{
    __shared__ float2 sc[TABLE];      // (c[i], c[i+1]) pairs, 26 KB
    __shared__ float2 ssc[NUM_ACT];   // (s, 1/s)

    for (int i = threadIdx.x; i < TABLE; i += 256) {
        float a = coef[i];
        float b = (i + 1 < TABLE) ? coef[i + 1] : 0.0f;   // edge slot never dereferenced
        sc[i] = make_float2(a, b);
    }
    if (threadIdx.x < NUM_ACT) {
        float s = scale[threadIdx.x];
        ssc[threadIdx.x] = make_float2(s, 1.0f / s);      // exact for s==1
    }
    __syncthreads();

    const float rg = 6.25f;
    const int stride = gridDim.x * blockDim.x;
    int i = blockIdx.x * blockDim.x + threadIdx.x;

    // One element: ~12 SASS ops + 1 LDS.64, zero divisions.
    #define ELEM(v, ov, zk_, s_, rs_) {                      \
        float xs = (v) * (s_);                               \
        float t  = xs * rg;                                  \
        float tc = fminf(fmaxf(t, -25.0f), 24.0f);           \
        float fl = floorf(tc);                               \
        float fr = t - fl;                                   \
        float2 cp = sc[(zk_) + (int)fl];                     \
        (ov) = fmaf(fr, cp.y - cp.x, cp.x) * (rs_); }

    // ILP=2: two independent float4 tiles in flight per trip.
    for (; i + stride < n4; i += 2 * stride) {
        const int j = i + stride;
        float4 xa = x[i];
        float4 xb = x[j];

        const int ca = (i >> 12) & (NUM_ACT - 1);   // 4096 float4 per channel
        const int cb = (j >> 12) & (NUM_ACT - 1);
        const float2 sva = ssc[ca];
        const float2 svb = ssc[cb];
        const int zka = ca * SIZE + SIZE / 2;
        const int zkb = cb * SIZE + SIZE / 2;

        float4 oa, ob;
        ELEM(xa.x, oa.x, zka, sva.x, sva.y)
        ELEM(xa.y, oa.y, zka, sva.x, sva.y)
        ELEM(xa.z, oa.z, zka, sva.x, sva.y)
        ELEM(xa.w, oa.w, zka, sva.x, sva.y)
        ELEM(xb.x, ob.x, zkb, svb.x, svb.y)
        ELEM(xb.y, ob.y, zkb, svb.x, svb.y)
        ELEM(xb.z, ob.z, zkb, svb.x, svb.y)
        ELEM(xb.w, ob.w, zkb, svb.x, svb.y)

        out[i] = oa;
        out[j] = ob;
    }
    // tail (at most one extra element per thread)
    if (i < n4) {
        float4 xv = x[i];
        const int c = (i >> 12) & (NUM_ACT - 1);
        const float2 sv = ssc[c];
        const int zk = c * SIZE + SIZE / 2;
        float4 o;
        ELEM(xv.x, o.x, zk, sv.x, sv.y)
        ELEM(xv.y, o.y, zk, sv.x, sv.y)
        ELEM(xv.z, o.z, zk, sv.x, sv.y)
        ELEM(xv.w, o.w, zk, sv.x, sv.y)
        out[i] = o;
    }
    #undef ELEM
}

extern "C" void kernel_launch(void* const* d_in, const int* in_sizes, int n_in,
                              void* d_out, int out_size)
{
    const float* x     = (const float*)d_in[0];
    const float* coef  = (const float*)d_in[1];
    const float* scale = (const float*)d_in[2];
    float* out         = (float*)d_out;

    const int n  = in_sizes[0];   // 33,554,432
    const int n4 = n / 4;         // 8,388,608

    const int threads = 256;
    const int blocks  = 148 * 6;  // 6 CTAs/SM (reg budget @ ILP=2), single wave

    linear_spline_kernel<<<blocks, threads>>>(
        (const float4*)x, coef, scale, (float4*)out, n4);
}